// round 6
// baseline (speedup 1.0000x reference)
#include <cuda_runtime.h>

// QuConv: out = U X U^dagger with U = Up^{kron 6} (Up 4x4 complex from 5
// weights), X real [4,4096,4096]. Separable: 12 radix-4 butterfly stages
// (6 column digits with conj(Up), 6 row digits with Up), 3 digits per pass.
//
// Output layout is determined EMPIRICALLY from out_size:
//   out_size >= 134217728  -> interleaved complex (float pairs), in-place on d_out
//   else                   -> real part only (float32); complex intermediate in
//                             a __device__ scratch, final pass stores re() only.
// All global extents are guarded per block against in_sizes/out_size.

typedef unsigned long long u64;
#define NQ 4096

__device__ float2 g_M[16];    // Up
__device__ float2 g_Mc[16];   // conj(Up)
__device__ float2 g_S[(size_t)4 * NQ * NQ];  // 512 MB scratch (real-only path)

// ---------------- packed f32x2 helpers ----------------
__device__ __forceinline__ u64 pk2(float a, float b){
    u64 r; asm("mov.b64 %0, {%1,%2};" : "=l"(r) : "f"(a), "f"(b)); return r;
}
__device__ __forceinline__ void upk2(u64 v, float& a, float& b){
    asm("mov.b64 {%0,%1}, %2;" : "=f"(a), "=f"(b) : "l"(v));
}
__device__ __forceinline__ u64 f2fma(u64 a, u64 b, u64 c){
    u64 d; asm("fma.rn.f32x2 %0, %1, %2, %3;" : "=l"(d) : "l"(a), "l"(b), "l"(c)); return d;
}
__device__ __forceinline__ u64 f2mul(u64 a, u64 b){
    u64 d; asm("mul.rn.f32x2 %0, %1, %2;" : "=l"(d) : "l"(a), "l"(b)); return d;
}
__device__ __forceinline__ u64 f2neg(u64 a){ return a ^ 0x8000000080000000ULL; }

struct C2 { u64 re, im; };

__device__ __forceinline__ void bfly4(C2& a0, C2& a1, C2& a2, C2& a3,
                                      const u64* __restrict__ mre,
                                      const u64* __restrict__ mim){
    C2 i0=a0, i1=a1, i2=a2, i3=a3;
    u64 n0=f2neg(i0.im), n1=f2neg(i1.im), n2=f2neg(i2.im), n3=f2neg(i3.im);
    C2 o[4];
#pragma unroll
    for(int r=0;r<4;r++){
        u64 re = f2mul(i0.re, mre[4*r+0]);
        re = f2fma(n0,    mim[4*r+0], re);
        re = f2fma(i1.re, mre[4*r+1], re);
        re = f2fma(n1,    mim[4*r+1], re);
        re = f2fma(i2.re, mre[4*r+2], re);
        re = f2fma(n2,    mim[4*r+2], re);
        re = f2fma(i3.re, mre[4*r+3], re);
        re = f2fma(n3,    mim[4*r+3], re);
        u64 im = f2mul(i0.im, mre[4*r+0]);
        im = f2fma(i0.re, mim[4*r+0], im);
        im = f2fma(i1.im, mre[4*r+1], im);
        im = f2fma(i1.re, mim[4*r+1], im);
        im = f2fma(i2.im, mre[4*r+2], im);
        im = f2fma(i2.re, mim[4*r+2], im);
        im = f2fma(i3.im, mre[4*r+3], im);
        im = f2fma(i3.re, mim[4*r+3], im);
        o[r].re = re; o[r].im = im;
    }
    a0=o[0]; a1=o[1]; a2=o[2]; a3=o[3];
}

__device__ __forceinline__ void bfly4r(const u64* __restrict__ xr, C2* __restrict__ v,
                                       const u64* __restrict__ mre,
                                       const u64* __restrict__ mim){
#pragma unroll
    for(int r=0;r<4;r++){
        u64 re = f2mul(xr[0], mre[4*r+0]);
        re = f2fma(xr[1], mre[4*r+1], re);
        re = f2fma(xr[2], mre[4*r+2], re);
        re = f2fma(xr[3], mre[4*r+3], re);
        u64 im = f2mul(xr[0], mim[4*r+0]);
        im = f2fma(xr[1], mim[4*r+1], im);
        im = f2fma(xr[2], mim[4*r+2], im);
        im = f2fma(xr[3], mim[4*r+3], im);
        v[r].re = re; v[r].im = im;
    }
}

__device__ __forceinline__ void digits2(C2* __restrict__ v,
                                        const u64* __restrict__ mre,
                                        const u64* __restrict__ mim){
#pragma unroll
    for(int g=0;g<4;g++) bfly4(v[4*g],v[4*g+1],v[4*g+2],v[4*g+3], mre, mim);
#pragma unroll
    for(int g=0;g<4;g++) bfly4(v[g],v[g+4],v[g+8],v[g+12], mre, mim);
}

// ---------------- K0: build Up / conj(Up) ----------------
__device__ __forceinline__ float2 cmulf(float2 a, float2 b){
    return make_float2(a.x*b.x - a.y*b.y, a.x*b.y + a.y*b.x);
}

__global__ void k_build(const float* __restrict__ w, long long wn){
    if (threadIdx.x != 0 || blockIdx.x != 0) return;
    if (wn < 5) return;
    const float WM = 0.63245553203367586f;  // sqrt(2/5)
    float th0=w[0]*WM, th1=w[1]*WM, th2=w[2]*WM, th3=w[3]*WM, th4=w[4]*WM;
    float c0=cosf(0.5f*th0), s0=sinf(0.5f*th0);
    float c1=cosf(0.5f*th1), s1=sinf(0.5f*th1);
    float c2=cosf(0.5f*th2), s2=sinf(0.5f*th2);
    float2 rx0[4] = { {c0,0.f},{0.f,-s0},{0.f,-s0},{c0,0.f} };
    float2 rx1[4] = { {c1,0.f},{0.f,-s1},{0.f,-s1},{c1,0.f} };
    float2 rx01[4];
    for(int a=0;a<2;a++) for(int c=0;c<2;c++){
        float2 sacc = make_float2(0.f,0.f);
        for(int k=0;k<2;k++){
            float2 p = cmulf(rx1[a*2+k], rx0[k*2+c]);
            sacc.x += p.x; sacc.y += p.y;
        }
        rx01[a*2+c] = sacc;
    }
    float2 A4[16];
    for(int i=0;i<16;i++) A4[i]=make_float2(0.f,0.f);
    for(int a=0;a<2;a++) for(int c=0;c<2;c++) for(int p=0;p<2;p++)
        A4[(2*a+p)*4 + (2*c+p)] = rx01[a*2+c];
    float2 G[16];
    for(int i=0;i<16;i++) G[i]=make_float2(0.f,0.f);
    G[0]=make_float2(c2,0.f); G[5]=make_float2(c2,0.f);
    G[10]=make_float2(c2,0.f); G[15]=make_float2(c2,0.f);
    G[0*4+3]=make_float2(0.f,  s2);
    G[3*4+0]=make_float2(0.f,  s2);
    G[1*4+2]=make_float2(0.f, -s2);
    G[2*4+1]=make_float2(0.f, -s2);
    float2 GA[16];
    for(int r=0;r<4;r++) for(int c=0;c<4;c++){
        float2 sacc=make_float2(0.f,0.f);
        for(int k=0;k<4;k++){
            float2 p=cmulf(G[r*4+k], A4[k*4+c]);
            sacc.x+=p.x; sacc.y+=p.y;
        }
        GA[r*4+c]=sacc;
    }
    float e3=0.5f*th3, e4=0.5f*th4;
    float2 dd[4];
    dd[0]=make_float2(cosf(e3+e4), -sinf(e3+e4));
    dd[1]=make_float2(cosf(e3-e4), -sinf(e3-e4));
    dd[2]=make_float2(dd[1].x, -dd[1].y);
    dd[3]=make_float2(dd[0].x, -dd[0].y);
    for(int r=0;r<4;r++) for(int c=0;c<4;c++){
        float2 u = cmulf(dd[r], GA[r*4+c]);
        g_M[r*4+c]=u;
        g_Mc[r*4+c]=make_float2(u.x, -u.y);
    }
}

// ---------------- kB: j digits 0..2, x(real) -> complex field -----------
// Tile 64 rows x 64 contiguous j; f32x2 lanes pack rows (ip, ip+32).
template<bool USE_S>
__global__ __launch_bounds__(128) void kB(const float* __restrict__ x,
                                          float2* __restrict__ oext,
                                          long long xlimf, long long olimf){
    float2* __restrict__ out = USE_S ? (float2*)g_S : oext;
    __shared__ u64 sbuf[4096];                 // 32 KB
    u64* sre = sbuf;
    u64* sim = sbuf + 2048;
    float* rf = reinterpret_cast<float*>(sbuf); // [64][69] staging, aliases sbuf
    int t = threadIdx.x;
    int jb = blockIdx.x * 64;
    long long R0 = (long long)blockIdx.y * 64;
    // guards: whole-block extents (uniform -> no divergence)
    if ((R0 + 64) * 4096LL > xlimf) return;
    if (!USE_S && 2LL * (R0 + 64) * 4096LL > olimf) return;
    u64 mre[16], mim[16];
#pragma unroll
    for(int e=0;e<16;e++){ float2 m=g_Mc[e]; mre[e]=pk2(m.x,m.x); mim[e]=pk2(m.y,m.y); }
    // stage 1: coalesced load of the 64x64 real tile (1024 float4s)
#pragma unroll
    for(int s=0;s<8;s++){
        int F = t + 128*s;
        int row = F >> 4, c4 = F & 15;
        float4 a = *reinterpret_cast<const float4*>(x + (R0+row)*4096 + jb + c4*4);
        int o = row*69 + c4*4;
        rf[o+0]=a.x; rf[o+1]=a.y; rf[o+2]=a.z; rf[o+3]=a.w;
    }
    __syncthreads();
    // stage 2: gather 16 coupled j for row pair (ip, ip+32)
    int g  = t >> 5;
    int ip = t & 31;
    u64 xr[16];
#pragma unroll
    for(int k=0;k<16;k++)
        xr[k] = pk2(rf[ip*69 + 16*g + k], rf[(ip+32)*69 + 16*g + k]);
    __syncthreads();                        // rf dead; sre/sim may alias it
    C2 v[16];
#pragma unroll
    for(int gg=0;gg<4;gg++) bfly4r(xr+4*gg, v+4*gg, mre, mim);   // j digit 0
#pragma unroll
    for(int gg=0;gg<4;gg++) bfly4(v[gg],v[gg+4],v[gg+8],v[gg+12], mre, mim); // j digit 1
#pragma unroll
    for(int k=0;k<16;k++){
        int jj = 16*g + k;
        int sidx = jj*32 + ((ip + jj) & 31);   // rotate swizzle
        sre[sidx] = v[k].re; sim[sidx] = v[k].im;
    }
    __syncthreads();
    // phase B: j digit 2 (stride 16), in place per slot
    {
        int lo0 = g*4;
#pragma unroll
        for(int q=0;q<4;q++){
            int lo = lo0 + q;
            C2 wv[4];
#pragma unroll
            for(int mm=0;mm<4;mm++){
                int jj = lo + 16*mm;
                int sidx = jj*32 + ((ip + jj) & 31);
                wv[mm].re = sre[sidx]; wv[mm].im = sim[sidx];
            }
            bfly4(wv[0],wv[1],wv[2],wv[3], mre, mim);
#pragma unroll
            for(int mm=0;mm<4;mm++){
                int jj = lo + 16*mm;
                int sidx = jj*32 + ((ip + jj) & 31);
                sre[sidx] = wv[mm].re; sim[sidx] = wv[mm].im;
            }
        }
    }
    __syncthreads();
    // write-out: coalesced float4 stores
#pragma unroll
    for(int s=0;s<16;s++){
        int F = t + 128*s;                 // 2048 float4s
        int row = F >> 5, c = F & 31;
        int rp2 = row & 31, h = row >> 5;
        int j0 = 2*c, j1 = 2*c+1;
        u64 a = sre[j0*32 + ((rp2+j0)&31)];
        u64 b = sim[j0*32 + ((rp2+j0)&31)];
        u64 cc= sre[j1*32 + ((rp2+j1)&31)];
        u64 d = sim[j1*32 + ((rp2+j1)&31)];
        float a0,a1,b0,b1,c0,c1,d0,d1;
        upk2(a,a0,a1); upk2(b,b0,b1); upk2(cc,c0,c1); upk2(d,d0,d1);
        float4 o = h ? make_float4(a1,b1,c1,d1) : make_float4(a0,b0,c0,d0);
        *reinterpret_cast<float4*>(out + (R0+row)*4096 + jb + j0) = o;
    }
}

// ---------------- kA<MODE>: 3 digits in place on complex field ----------
// MODE 0: j digits 3..5 (CS=64, conj(Up)). MODE 1: i digits 0..2 (CS=4096, Up).
// MODE 2: i digits 3..5 (CS=262144, Up).
template<int MODE, bool USE_S>
__global__ __launch_bounds__(128) void kA(float2* __restrict__ pext, long long olimf){
    constexpr long long CS = (MODE==0) ? 64 : (MODE==1 ? 4096 : 262144);
    float2* __restrict__ p = USE_S ? (float2*)g_S : pext;
    __shared__ u64 sre[2048];
    __shared__ u64 sim[2048];
    u64 mre[16], mim[16];
    const float2* Mp = (MODE==0) ? g_Mc : g_M;
#pragma unroll
    for(int e=0;e<16;e++){ float2 m=Mp[e]; mre[e]=pk2(m.x,m.x); mim[e]=pk2(m.y,m.y); }
    int t = threadIdx.x;
    long long base;
    if (MODE==0)      base = (long long)blockIdx.x * 4096LL;
    else if (MODE==1) base = ((long long)(blockIdx.z*4096 + blockIdx.y*64))*4096LL + blockIdx.x*64;
    else              base = ((long long)(blockIdx.z*4096 + blockIdx.y))*4096LL + blockIdx.x*64;
    if (!USE_S && 2LL*(base + 63*CS + 64) > olimf) return;
    int jp = t & 31;
    int g  = t >> 5;
    C2 v[16];
#pragma unroll
    for(int k=0;k<16;k++){
        long long m = 16*g + k;
        float4 d4 = *reinterpret_cast<const float4*>(p + base + m*CS + 2*jp);
        v[k].re = pk2(d4.x, d4.z);
        v[k].im = pk2(d4.y, d4.w);
    }
    digits2(v, mre, mim);
#pragma unroll
    for(int k=0;k<16;k++){ int m=16*g+k; sre[m*32+jp]=v[k].re; sim[m*32+jp]=v[k].im; }
    __syncthreads();
    int lo0 = g*4;
#pragma unroll
    for(int q=0;q<4;q++){
        int lo = lo0 + q;
        C2 wv[4];
#pragma unroll
        for(int mm=0;mm<4;mm++){ int m=lo+16*mm; wv[mm].re=sre[m*32+jp]; wv[mm].im=sim[m*32+jp]; }
        bfly4(wv[0],wv[1],wv[2],wv[3], mre, mim);
#pragma unroll
        for(int mm=0;mm<4;mm++){
            long long m = lo + 16*mm;
            float r0,r1,i0,i1;
            upk2(wv[mm].re,r0,r1); upk2(wv[mm].im,i0,i1);
            float4 o = make_float4(r0,i0,r1,i1);
            *reinterpret_cast<float4*>(p + base + m*CS + 2*jp) = o;
        }
    }
}

// ---- kA2r: like kA<2> on g_S, but store ONLY real parts to float out ----
__global__ __launch_bounds__(128) void kA2r(float* __restrict__ outf, long long olimf){
    constexpr long long CS = 262144;
    const float2* __restrict__ p = g_S;
    __shared__ u64 sre[2048];
    __shared__ u64 sim[2048];
    u64 mre[16], mim[16];
#pragma unroll
    for(int e=0;e<16;e++){ float2 m=g_M[e]; mre[e]=pk2(m.x,m.x); mim[e]=pk2(m.y,m.y); }
    int t = threadIdx.x;
    long long base = ((long long)(blockIdx.z*4096 + blockIdx.y))*4096LL + blockIdx.x*64;
    if (base + 63*CS + 64 > olimf) return;   // out floats == complex-field indices here
    int jp = t & 31;
    int g  = t >> 5;
    C2 v[16];
#pragma unroll
    for(int k=0;k<16;k++){
        long long m = 16*g + k;
        float4 d4 = *reinterpret_cast<const float4*>(p + base + m*CS + 2*jp);
        v[k].re = pk2(d4.x, d4.z);
        v[k].im = pk2(d4.y, d4.w);
    }
    digits2(v, mre, mim);
#pragma unroll
    for(int k=0;k<16;k++){ int m=16*g+k; sre[m*32+jp]=v[k].re; sim[m*32+jp]=v[k].im; }
    __syncthreads();
    int lo0 = g*4;
#pragma unroll
    for(int q=0;q<4;q++){
        int lo = lo0 + q;
        C2 wv[4];
#pragma unroll
        for(int mm=0;mm<4;mm++){ int m=lo+16*mm; wv[mm].re=sre[m*32+jp]; wv[mm].im=sim[m*32+jp]; }
        bfly4(wv[0],wv[1],wv[2],wv[3], mre, mim);
#pragma unroll
        for(int mm=0;mm<4;mm++){
            long long m = lo + 16*mm;
            float r0,r1,i0,i1;
            upk2(wv[mm].re,r0,r1); upk2(wv[mm].im,i0,i1);
            (void)i0; (void)i1;
            *reinterpret_cast<float2*>(outf + base + m*CS + 2*jp) = make_float2(r0,r1);
        }
    }
}

// ---------------- launch ----------------
extern "C" void kernel_launch(void* const* d_in, const int* in_sizes, int n_in,
                              void* d_out, int out_size){
    // identify inputs: w = smallest, x = largest
    int xi = 0, wi = 0;
    for (int i = 1; i < n_in; i++){
        if (in_sizes[i] > in_sizes[xi]) xi = i;
        if (in_sizes[i] < in_sizes[wi]) wi = i;
    }
    if (xi == wi && n_in >= 2) wi = (xi == 0) ? 1 : 0;
    const float* x = (const float*)d_in[xi];
    const float* w = (const float*)d_in[wi];
    long long xlim = (long long)in_sizes[xi];
    long long wlim = (long long)in_sizes[wi];
    long long olim = (long long)out_size;

    k_build<<<1, 32>>>(w, wlim);

    bool interleaved = (olim >= 134217728LL);
    if (interleaved){
        float2* out = (float2*)d_out;
        kB<false><<<dim3(64, 256), 128>>>(x, out, xlim, olim);   // j digits 0..2
        kA<0,false><<<16384, 128>>>(out, olim);                  // j digits 3..5
        kA<1,false><<<dim3(64, 64, 4), 128>>>(out, olim);        // i digits 0..2
        kA<2,false><<<dim3(64, 64, 4), 128>>>(out, olim);        // i digits 3..5
    } else {
        // real-part-only output: run the complex pipeline in g_S
        kB<true><<<dim3(64, 256), 128>>>(x, nullptr, xlim, 0);   // j digits 0..2
        kA<0,true><<<16384, 128>>>(nullptr, 0);                  // j digits 3..5
        kA<1,true><<<dim3(64, 64, 4), 128>>>(nullptr, 0);        // i digits 0..2
        kA2r<<<dim3(64, 64, 4), 128>>>((float*)d_out, olim);     // i digits 3..5 -> re()
    }
}